// round 4
// baseline (speedup 1.0000x reference)
#include <cuda_runtime.h>
#include <cuda_bf16.h>
#include <math.h>

#define Nn 50000
#define Ee 800000
#define Hh 128
#define Gg 512
#define BN_EPS 1e-5f

#define MS 64          // rows per MLP tile
#define AS 132         // padded row stride (floats) for A/B smem tiles
#define NTILES ((Nn + MS - 1) / MS)

// ---------------- scratch (static device memory; no runtime alloc) ----------
__device__ int   g_deg[Nn];
__device__ int   g_rowoff[Nn + 1];
__device__ int   g_cursor[Nn];
__device__ int   g_col[Ee];
__device__ float g_T2[Nn * 2];
__device__ float g_bufA[Nn * Hh];
__device__ float g_T[Nn * Hh];
__device__ float g_pooled[Gg * Hh];

// ---------------- setup kernels ---------------------------------------------
__global__ void zero_kernel() {
    int i = blockIdx.x * blockDim.x + threadIdx.x;
    if (i < Nn) g_deg[i] = 0;
    if (i < Gg * Hh) g_pooled[i] = 0.0f;
}

__global__ void hist_kernel(const int* __restrict__ ei) {
    int e = blockIdx.x * blockDim.x + threadIdx.x;
    if (e < Ee) {
        int d = ei[Ee + e];
        atomicAdd(&g_deg[d], 1);
    }
}

// single block, 1024 threads: exclusive scan of g_deg -> g_rowoff, g_cursor
__global__ void scan_kernel() {
    const int C = (Nn + 1023) / 1024;  // 49
    int t = threadIdx.x;
    int base = t * C;
    int sum = 0;
    for (int i = 0; i < C; i++) {
        int idx = base + i;
        if (idx < Nn) sum += g_deg[idx];
    }
    __shared__ int sh[1024];
    sh[t] = sum;
    __syncthreads();
    for (int off = 1; off < 1024; off <<= 1) {
        int v = (t >= off) ? sh[t - off] : 0;
        __syncthreads();
        sh[t] += v;
        __syncthreads();
    }
    int run = (t == 0) ? 0 : sh[t - 1];
    for (int i = 0; i < C; i++) {
        int idx = base + i;
        if (idx < Nn) {
            g_rowoff[idx] = run;
            g_cursor[idx] = run;
            run += g_deg[idx];
        }
    }
    if (t == 1023) g_rowoff[Nn] = sh[1023];
}

__global__ void fill_kernel(const int* __restrict__ ei) {
    int e = blockIdx.x * blockDim.x + threadIdx.x;
    if (e < Ee) {
        int s = ei[e];
        int d = ei[Ee + e];
        int pos = atomicAdd(&g_cursor[d], 1);
        g_col[pos] = s;
    }
}

// ---------------- aggregation -----------------------------------------------
// layer 1: d=2, thread per node: T2[i] = x[i] + sum_{j in nbr(i)} x[j]
__global__ void agg2_kernel(const float* __restrict__ x) {
    int i = blockIdx.x * blockDim.x + threadIdx.x;
    if (i >= Nn) return;
    const float2* x2 = (const float2*)x;
    float2 acc = x2[i];
    int s = g_rowoff[i], e = g_rowoff[i + 1];
    for (int k = s; k < e; k++) {
        int j = g_col[k];
        float2 v = x2[j];
        acc.x += v.x; acc.y += v.y;
    }
    ((float2*)g_T2)[i] = acc;
}

// H=128: one warp per node, float4 per lane
__global__ void agg128_kernel(const float* __restrict__ in, float* __restrict__ out) {
    int gtid = blockIdx.x * blockDim.x + threadIdx.x;
    int node = gtid >> 5;
    int lane = gtid & 31;
    if (node >= Nn) return;
    const float4* in4 = (const float4*)in;
    float4 acc = in4[node * 32 + lane];
    int s = g_rowoff[node], e = g_rowoff[node + 1];
    for (int k = s; k < e; k++) {
        int j = g_col[k];
        float4 v = __ldg(&in4[j * 32 + lane]);
        acc.x += v.x; acc.y += v.y; acc.z += v.z; acc.w += v.w;
    }
    ((float4*)out)[node * 32 + lane] = acc;
}

// ---------------- fused MLP (two 128x128 GEMMs + relu + BN) ------------------
// grid: NTILES blocks of 256 threads. smem: W1(16384)+W2(16384)+As(64*132)+Bs(64*132)
extern "C" __global__ void __launch_bounds__(256, 1)
mlp_fused(const float* __restrict__ in, float* __restrict__ out,
          const float* __restrict__ W1, const float* __restrict__ b1,
          const float* __restrict__ W2, const float* __restrict__ b2,
          const float* __restrict__ gamma, const float* __restrict__ beta,
          const float* __restrict__ mean, const float* __restrict__ var) {
    extern __shared__ float sm[];
    float* Ws1 = sm;
    float* Ws2 = sm + 16384;
    float* Asm = sm + 32768;
    float* Bsm = Asm + MS * AS;

    int tid = threadIdx.x;
    // stage weights
    for (int i = tid; i < 4096; i += 256) {
        ((float4*)Ws1)[i] = ((const float4*)W1)[i];
        ((float4*)Ws2)[i] = ((const float4*)W2)[i];
    }
    // stage A tile
    int row0 = blockIdx.x * MS;
    for (int f = tid; f < MS * 32; f += 256) {
        int r = f >> 5, k4 = f & 31;
        float4 v = make_float4(0.f, 0.f, 0.f, 0.f);
        if (row0 + r < Nn) v = ((const float4*)in)[(row0 + r) * 32 + k4];
        *(float4*)&Asm[r * AS + k4 * 4] = v;
    }
    __syncthreads();

    int tcol = tid & 15;
    int trow = tid >> 4;
    int c0 = tcol * 8;
    int r0 = trow * 4;

    float acc[4][8];
    // ---- GEMM1: B = relu(A @ W1 + b1) ----
    {
        float4 bb0 = *(const float4*)&b1[c0];
        float4 bb1 = *(const float4*)&b1[c0 + 4];
        #pragma unroll
        for (int i = 0; i < 4; i++) {
            acc[i][0] = bb0.x; acc[i][1] = bb0.y; acc[i][2] = bb0.z; acc[i][3] = bb0.w;
            acc[i][4] = bb1.x; acc[i][5] = bb1.y; acc[i][6] = bb1.z; acc[i][7] = bb1.w;
        }
        #pragma unroll 4
        for (int k = 0; k < 128; k++) {
            float a[4];
            #pragma unroll
            for (int i = 0; i < 4; i++) a[i] = Asm[(r0 + i) * AS + k];
            float4 w0 = *(float4*)&Ws1[k * 128 + c0];
            float4 w1 = *(float4*)&Ws1[k * 128 + c0 + 4];
            #pragma unroll
            for (int i = 0; i < 4; i++) {
                acc[i][0] = fmaf(a[i], w0.x, acc[i][0]);
                acc[i][1] = fmaf(a[i], w0.y, acc[i][1]);
                acc[i][2] = fmaf(a[i], w0.z, acc[i][2]);
                acc[i][3] = fmaf(a[i], w0.w, acc[i][3]);
                acc[i][4] = fmaf(a[i], w1.x, acc[i][4]);
                acc[i][5] = fmaf(a[i], w1.y, acc[i][5]);
                acc[i][6] = fmaf(a[i], w1.z, acc[i][6]);
                acc[i][7] = fmaf(a[i], w1.w, acc[i][7]);
            }
        }
        #pragma unroll
        for (int i = 0; i < 4; i++) {
            #pragma unroll
            for (int j = 0; j < 8; j++) acc[i][j] = fmaxf(acc[i][j], 0.f);
            *(float4*)&Bsm[(r0 + i) * AS + c0]     = make_float4(acc[i][0], acc[i][1], acc[i][2], acc[i][3]);
            *(float4*)&Bsm[(r0 + i) * AS + c0 + 4] = make_float4(acc[i][4], acc[i][5], acc[i][6], acc[i][7]);
        }
    }
    __syncthreads();

    // ---- GEMM2: C = BN(relu(B @ W2 + b2)) ----
    {
        float4 bb0 = *(const float4*)&b2[c0];
        float4 bb1 = *(const float4*)&b2[c0 + 4];
        #pragma unroll
        for (int i = 0; i < 4; i++) {
            acc[i][0] = bb0.x; acc[i][1] = bb0.y; acc[i][2] = bb0.z; acc[i][3] = bb0.w;
            acc[i][4] = bb1.x; acc[i][5] = bb1.y; acc[i][6] = bb1.z; acc[i][7] = bb1.w;
        }
        #pragma unroll 4
        for (int k = 0; k < 128; k++) {
            float a[4];
            #pragma unroll
            for (int i = 0; i < 4; i++) a[i] = Bsm[(r0 + i) * AS + k];
            float4 w0 = *(float4*)&Ws2[k * 128 + c0];
            float4 w1 = *(float4*)&Ws2[k * 128 + c0 + 4];
            #pragma unroll
            for (int i = 0; i < 4; i++) {
                acc[i][0] = fmaf(a[i], w0.x, acc[i][0]);
                acc[i][1] = fmaf(a[i], w0.y, acc[i][1]);
                acc[i][2] = fmaf(a[i], w0.z, acc[i][2]);
                acc[i][3] = fmaf(a[i], w0.w, acc[i][3]);
                acc[i][4] = fmaf(a[i], w1.x, acc[i][4]);
                acc[i][5] = fmaf(a[i], w1.y, acc[i][5]);
                acc[i][6] = fmaf(a[i], w1.z, acc[i][6]);
                acc[i][7] = fmaf(a[i], w1.w, acc[i][7]);
            }
        }
        // epilogue: relu then BN affine
        float4 gm0 = *(const float4*)&gamma[c0], gm1 = *(const float4*)&gamma[c0 + 4];
        float4 bt0 = *(const float4*)&beta[c0],  bt1 = *(const float4*)&beta[c0 + 4];
        float4 mn0 = *(const float4*)&mean[c0],  mn1 = *(const float4*)&mean[c0 + 4];
        float4 vr0 = *(const float4*)&var[c0],   vr1 = *(const float4*)&var[c0 + 4];
        float scl[8], mu[8], bt[8];
        scl[0]=gm0.x*rsqrtf(vr0.x+BN_EPS); scl[1]=gm0.y*rsqrtf(vr0.y+BN_EPS);
        scl[2]=gm0.z*rsqrtf(vr0.z+BN_EPS); scl[3]=gm0.w*rsqrtf(vr0.w+BN_EPS);
        scl[4]=gm1.x*rsqrtf(vr1.x+BN_EPS); scl[5]=gm1.y*rsqrtf(vr1.y+BN_EPS);
        scl[6]=gm1.z*rsqrtf(vr1.z+BN_EPS); scl[7]=gm1.w*rsqrtf(vr1.w+BN_EPS);
        mu[0]=mn0.x; mu[1]=mn0.y; mu[2]=mn0.z; mu[3]=mn0.w;
        mu[4]=mn1.x; mu[5]=mn1.y; mu[6]=mn1.z; mu[7]=mn1.w;
        bt[0]=bt0.x; bt[1]=bt0.y; bt[2]=bt0.z; bt[3]=bt0.w;
        bt[4]=bt1.x; bt[5]=bt1.y; bt[6]=bt1.z; bt[7]=bt1.w;
        #pragma unroll
        for (int i = 0; i < 4; i++) {
            int row = row0 + r0 + i;
            if (row < Nn) {
                float o[8];
                #pragma unroll
                for (int j = 0; j < 8; j++) {
                    float v = fmaxf(acc[i][j], 0.f);
                    o[j] = (v - mu[j]) * scl[j] + bt[j];
                }
                *(float4*)&out[row * 128 + c0]     = make_float4(o[0], o[1], o[2], o[3]);
                *(float4*)&out[row * 128 + c0 + 4] = make_float4(o[4], o[5], o[6], o[7]);
            }
        }
    }
}

// ---------------- layer 1 MLP (input dim 2) ----------------------------------
extern "C" __global__ void __launch_bounds__(256, 1)
layer1_mlp(float* __restrict__ out,
           const float* __restrict__ W1, const float* __restrict__ b1,
           const float* __restrict__ W2, const float* __restrict__ b2,
           const float* __restrict__ gamma, const float* __restrict__ beta,
           const float* __restrict__ mean, const float* __restrict__ var) {
    extern __shared__ float sm[];
    float* Ws2 = sm;                 // 16384
    float* Bsm = sm + 16384;         // 64*132
    float* tt  = Bsm + MS * AS;      // 128

    int tid = threadIdx.x;
    for (int i = tid; i < 4096; i += 256)
        ((float4*)Ws2)[i] = ((const float4*)W2)[i];

    int row0 = blockIdx.x * MS;
    if (tid < 128) {
        int r = tid >> 1;
        tt[tid] = (row0 + r < Nn) ? g_T2[row0 * 2 + tid] : 0.f;
    }
    __syncthreads();

    int tcol = tid & 15;
    int trow = tid >> 4;
    int c0 = tcol * 8;
    int r0 = trow * 4;

    // B = relu(t @ W1[2x128] + b1)
    {
        float4 wa0 = *(const float4*)&W1[c0];
        float4 wa1 = *(const float4*)&W1[c0 + 4];
        float4 wb0 = *(const float4*)&W1[128 + c0];
        float4 wb1 = *(const float4*)&W1[128 + c0 + 4];
        float4 bb0 = *(const float4*)&b1[c0];
        float4 bb1 = *(const float4*)&b1[c0 + 4];
        #pragma unroll
        for (int i = 0; i < 4; i++) {
            float t0 = tt[(r0 + i) * 2];
            float t1 = tt[(r0 + i) * 2 + 1];
            float o[8];
            o[0] = fmaf(t0, wa0.x, fmaf(t1, wb0.x, bb0.x));
            o[1] = fmaf(t0, wa0.y, fmaf(t1, wb0.y, bb0.y));
            o[2] = fmaf(t0, wa0.z, fmaf(t1, wb0.z, bb0.z));
            o[3] = fmaf(t0, wa0.w, fmaf(t1, wb0.w, bb0.w));
            o[4] = fmaf(t0, wa1.x, fmaf(t1, wb1.x, bb1.x));
            o[5] = fmaf(t0, wa1.y, fmaf(t1, wb1.y, bb1.y));
            o[6] = fmaf(t0, wa1.z, fmaf(t1, wb1.z, bb1.z));
            o[7] = fmaf(t0, wa1.w, fmaf(t1, wb1.w, bb1.w));
            #pragma unroll
            for (int j = 0; j < 8; j++) o[j] = fmaxf(o[j], 0.f);
            *(float4*)&Bsm[(r0 + i) * AS + c0]     = make_float4(o[0], o[1], o[2], o[3]);
            *(float4*)&Bsm[(r0 + i) * AS + c0 + 4] = make_float4(o[4], o[5], o[6], o[7]);
        }
    }
    __syncthreads();

    // GEMM2 + relu + BN
    float acc[4][8];
    {
        float4 bb0 = *(const float4*)&b2[c0];
        float4 bb1 = *(const float4*)&b2[c0 + 4];
        #pragma unroll
        for (int i = 0; i < 4; i++) {
            acc[i][0] = bb0.x; acc[i][1] = bb0.y; acc[i][2] = bb0.z; acc[i][3] = bb0.w;
            acc[i][4] = bb1.x; acc[i][5] = bb1.y; acc[i][6] = bb1.z; acc[i][7] = bb1.w;
        }
        #pragma unroll 4
        for (int k = 0; k < 128; k++) {
            float a[4];
            #pragma unroll
            for (int i = 0; i < 4; i++) a[i] = Bsm[(r0 + i) * AS + k];
            float4 w0 = *(float4*)&Ws2[k * 128 + c0];
            float4 w1 = *(float4*)&Ws2[k * 128 + c0 + 4];
            #pragma unroll
            for (int i = 0; i < 4; i++) {
                acc[i][0] = fmaf(a[i], w0.x, acc[i][0]);
                acc[i][1] = fmaf(a[i], w0.y, acc[i][1]);
                acc[i][2] = fmaf(a[i], w0.z, acc[i][2]);
                acc[i][3] = fmaf(a[i], w0.w, acc[i][3]);
                acc[i][4] = fmaf(a[i], w1.x, acc[i][4]);
                acc[i][5] = fmaf(a[i], w1.y, acc[i][5]);
                acc[i][6] = fmaf(a[i], w1.z, acc[i][6]);
                acc[i][7] = fmaf(a[i], w1.w, acc[i][7]);
            }
        }
        float scl[8], mu[8], bt[8];
        {
            float4 gm0 = *(const float4*)&gamma[c0], gm1 = *(const float4*)&gamma[c0 + 4];
            float4 bt0 = *(const float4*)&beta[c0],  bt1 = *(const float4*)&beta[c0 + 4];
            float4 mn0 = *(const float4*)&mean[c0],  mn1 = *(const float4*)&mean[c0 + 4];
            float4 vr0 = *(const float4*)&var[c0],   vr1 = *(const float4*)&var[c0 + 4];
            scl[0]=gm0.x*rsqrtf(vr0.x+BN_EPS); scl[1]=gm0.y*rsqrtf(vr0.y+BN_EPS);
            scl[2]=gm0.z*rsqrtf(vr0.z+BN_EPS); scl[3]=gm0.w*rsqrtf(vr0.w+BN_EPS);
            scl[4]=gm1.x*rsqrtf(vr1.x+BN_EPS); scl[5]=gm1.y*rsqrtf(vr1.y+BN_EPS);
            scl[6]=gm1.z*rsqrtf(vr1.z+BN_EPS); scl[7]=gm1.w*rsqrtf(vr1.w+BN_EPS);
            mu[0]=mn0.x; mu[1]=mn0.y; mu[2]=mn0.z; mu[3]=mn0.w;
            mu[4]=mn1.x; mu[5]=mn1.y; mu[6]=mn1.z; mu[7]=mn1.w;
            bt[0]=bt0.x; bt[1]=bt0.y; bt[2]=bt0.z; bt[3]=bt0.w;
            bt[4]=bt1.x; bt[5]=bt1.y; bt[6]=bt1.z; bt[7]=bt1.w;
        }
        #pragma unroll
        for (int i = 0; i < 4; i++) {
            int row = row0 + r0 + i;
            if (row < Nn) {
                float o[8];
                #pragma unroll
                for (int j = 0; j < 8; j++) {
                    float v = fmaxf(acc[i][j], 0.f);
                    o[j] = (v - mu[j]) * scl[j] + bt[j];
                }
                *(float4*)&out[row * 128 + c0]     = make_float4(o[0], o[1], o[2], o[3]);
                *(float4*)&out[row * 128 + c0 + 4] = make_float4(o[4], o[5], o[6], o[7]);
            }
        }
    }
}

// ---------------- pooling + head ---------------------------------------------
__global__ void pool_kernel(const float* __restrict__ h, const int* __restrict__ batch) {
    int gtid = blockIdx.x * blockDim.x + threadIdx.x;
    int node = gtid >> 5;
    int lane = gtid & 31;
    if (node >= Nn) return;
    int g = batch[node];
    float4 v = ((const float4*)h)[node * 32 + lane];
    float* dst = &g_pooled[g * 128 + lane * 4];
    atomicAdd(dst + 0, v.x);
    atomicAdd(dst + 1, v.y);
    atomicAdd(dst + 2, v.z);
    atomicAdd(dst + 3, v.w);
}

__global__ void head_kernel(const float* __restrict__ lin1W, const float* __restrict__ lin1b,
                            const float* __restrict__ lin2W, const float* __restrict__ lin2b,
                            float* __restrict__ out) {
    int g = blockIdx.x;
    int c = threadIdx.x;          // 128 threads
    __shared__ float p[128];
    p[c] = g_pooled[g * 128 + c];
    __syncthreads();
    float v = lin1b[c];
    #pragma unroll 8
    for (int k = 0; k < 128; k++)
        v = fmaf(p[k], lin1W[k * 128 + c], v);
    float partial = fmaxf(v, 0.f) * lin2W[c];
    #pragma unroll
    for (int off = 16; off > 0; off >>= 1)
        partial += __shfl_down_sync(0xffffffffu, partial, off);
    __shared__ float red[4];
    int warp = c >> 5;
    if ((c & 31) == 0) red[warp] = partial;
    __syncthreads();
    if (c == 0)
        out[g] = red[0] + red[1] + red[2] + red[3] + lin2b[0];
}

// ---------------- launcher ----------------------------------------------------
extern "C" void kernel_launch(void* const* d_in, const int* in_sizes, int n_in,
                              void* d_out, int out_size) {
    const float* x      = (const float*)d_in[0];
    const int*   ei     = (const int*)d_in[1];      // int32! (JAX x64 disabled)
    const int*   batch  = (const int*)d_in[2];      // int32!
    const float* c1_W1   = (const float*)d_in[3];
    const float* c1_b1   = (const float*)d_in[4];
    const float* c1_W2   = (const float*)d_in[5];
    const float* c1_b2   = (const float*)d_in[6];
    const float* c1_g    = (const float*)d_in[7];
    const float* c1_be   = (const float*)d_in[8];
    const float* c1_m    = (const float*)d_in[9];
    const float* c1_v    = (const float*)d_in[10];
    const float* cs_W1   = (const float*)d_in[11];
    const float* cs_b1   = (const float*)d_in[12];
    const float* cs_W2   = (const float*)d_in[13];
    const float* cs_b2   = (const float*)d_in[14];
    const float* cs_g    = (const float*)d_in[15];
    const float* cs_be   = (const float*)d_in[16];
    const float* cs_m    = (const float*)d_in[17];
    const float* cs_v    = (const float*)d_in[18];
    const float* lin1W   = (const float*)d_in[19];
    const float* lin1b   = (const float*)d_in[20];
    const float* lin2W   = (const float*)d_in[21];
    const float* lin2b   = (const float*)d_in[22];
    float* out = (float*)d_out;

    // Resolve device addresses of __device__ scratch (host-side symbol lookup;
    // not an allocation; graph-capture safe).
    float *pBufA = nullptr, *pT = nullptr;
    cudaGetSymbolAddress((void**)&pBufA, g_bufA);
    cudaGetSymbolAddress((void**)&pT, g_T);

    const int SMEM_FUSED = (16384 * 2 + 2 * MS * AS) * 4;   // 198656 B
    const int SMEM_L1    = (16384 + MS * AS + 128) * 4;     //  99840 B
    cudaFuncSetAttribute(mlp_fused, cudaFuncAttributeMaxDynamicSharedMemorySize, SMEM_FUSED);
    cudaFuncSetAttribute(layer1_mlp, cudaFuncAttributeMaxDynamicSharedMemorySize, SMEM_L1);

    // scratch reset + CSR build (per call; deterministic work)
    zero_kernel<<<(Gg * Hh + 255) / 256, 256>>>();
    hist_kernel<<<(Ee + 255) / 256, 256>>>(ei);
    scan_kernel<<<1, 1024>>>();
    fill_kernel<<<(Ee + 255) / 256, 256>>>(ei);

    // layer 1
    agg2_kernel<<<(Nn + 255) / 256, 256>>>(x);
    layer1_mlp<<<NTILES, 256, SMEM_L1>>>(pBufA, c1_W1, c1_b1, c1_W2, c1_b2,
                                         c1_g, c1_be, c1_m, c1_v);
    // layers 2..5
    const int HH = Hh * Hh;
    for (int l = 0; l < 4; l++) {
        agg128_kernel<<<(Nn * 32 + 255) / 256, 256>>>(pBufA, pT);
        mlp_fused<<<NTILES, 256, SMEM_FUSED>>>(pT, pBufA,
                                               cs_W1 + l * HH, cs_b1 + l * Hh,
                                               cs_W2 + l * HH, cs_b2 + l * Hh,
                                               cs_g + l * Hh, cs_be + l * Hh,
                                               cs_m + l * Hh, cs_v + l * Hh);
    }

    // pool + head
    pool_kernel<<<(Nn * 32 + 255) / 256, 256>>>(pBufA, batch);
    head_kernel<<<Gg, 128>>>(lin1W, lin1b, lin2W, lin2b, out);

    (void)in_sizes; (void)n_in; (void)out_size;
}

// round 7
// speedup vs baseline: 1.1376x; 1.1376x over previous
#include <cuda_runtime.h>
#include <cuda_bf16.h>
#include <math.h>

#define Nn 50000
#define Ee 800000
#define Hh 128
#define Gg 512
#define BN_EPS 1e-5f

// layer1 tile params (unchanged path)
#define MS 64
#define AS 132
#define NTILES ((Nn + MS - 1) / MS)

// persistent fused-layer params
#define TR 128                 // rows per tile
#define TSTR 132               // padded smem row stride (floats)
#define NT2 ((Nn + TR - 1) / TR)   // 391
#define NCTA 152

// ---------------- scratch ----------------------------------------------------
__device__ int   g_deg[Nn];
__device__ int   g_rowoff[Nn + 1];
__device__ int   g_cursor[Nn];
__device__ int   g_col[Ee];
__device__ float g_T2[Nn * 2];
__device__ float g_bufA[Nn * Hh];
__device__ float g_T[Nn * Hh];
__device__ float g_pooled[Gg * Hh];

// ---------------- f32x2 helpers ----------------------------------------------
__device__ __forceinline__ unsigned long long pack_dup(float a) {
    unsigned long long d;
    unsigned int r = __float_as_uint(a);
    asm("mov.b64 %0, {%1, %1};" : "=l"(d) : "r"(r));
    return d;
}
__device__ __forceinline__ unsigned long long pack2(float lo, float hi) {
    unsigned long long d;
    asm("mov.b64 %0, {%1, %2};" : "=l"(d) : "r"(__float_as_uint(lo)), "r"(__float_as_uint(hi)));
    return d;
}
__device__ __forceinline__ float2 unpack2(unsigned long long v) {
    unsigned int lo, hi;
    asm("mov.b64 {%0, %1}, %2;" : "=r"(lo), "=r"(hi) : "l"(v));
    return make_float2(__uint_as_float(lo), __uint_as_float(hi));
}
#define FMA2(acc, a, w) asm("fma.rn.f32x2 %0, %1, %2, %0;" : "+l"(acc) : "l"(a), "l"(w))

// ---------------- setup kernels ---------------------------------------------
__global__ void zero_kernel() {
    int i = blockIdx.x * blockDim.x + threadIdx.x;
    if (i < Nn) g_deg[i] = 0;
    if (i < Gg * Hh) g_pooled[i] = 0.0f;
}

__global__ void hist_kernel(const int* __restrict__ ei) {
    int e = blockIdx.x * blockDim.x + threadIdx.x;
    if (e < Ee) atomicAdd(&g_deg[ei[Ee + e]], 1);
}

__global__ void scan_kernel() {
    const int C = (Nn + 1023) / 1024;
    int t = threadIdx.x;
    int base = t * C;
    int sum = 0;
    for (int i = 0; i < C; i++) {
        int idx = base + i;
        if (idx < Nn) sum += g_deg[idx];
    }
    __shared__ int sh[1024];
    sh[t] = sum;
    __syncthreads();
    for (int off = 1; off < 1024; off <<= 1) {
        int v = (t >= off) ? sh[t - off] : 0;
        __syncthreads();
        sh[t] += v;
        __syncthreads();
    }
    int run = (t == 0) ? 0 : sh[t - 1];
    for (int i = 0; i < C; i++) {
        int idx = base + i;
        if (idx < Nn) {
            g_rowoff[idx] = run;
            g_cursor[idx] = run;
            run += g_deg[idx];
        }
    }
    if (t == 1023) g_rowoff[Nn] = sh[1023];
}

__global__ void fill_kernel(const int* __restrict__ ei) {
    int e = blockIdx.x * blockDim.x + threadIdx.x;
    if (e < Ee) {
        int s = ei[e];
        int d = ei[Ee + e];
        int pos = atomicAdd(&g_cursor[d], 1);
        g_col[pos] = s;
    }
}

// ---------------- layer-1 aggregation (d=2) -----------------------------------
__global__ void agg2_kernel(const float* __restrict__ x) {
    int i = blockIdx.x * blockDim.x + threadIdx.x;
    if (i >= Nn) return;
    const float2* x2 = (const float2*)x;
    float2 acc = x2[i];
    int s = g_rowoff[i], e = g_rowoff[i + 1];
    for (int k = s; k < e; k++) {
        float2 v = x2[g_col[k]];
        acc.x += v.x; acc.y += v.y;
    }
    ((float2*)g_T2)[i] = acc;
}

// ---------------- persistent fused GIN layer (layers 2..5) -------------------
// grid = NCTA persistent CTAs of 256 threads.
// smem: W1 (16384 f) + W2 (16384 f) + tile (128*132 f) = 198656 B
// Per tile: gather-aggregate A, GEMM1 (FFMA2) + relu -> smem, GEMM2 + relu + BN
// -> global out, or grouped atomic pool on the last layer.
extern "C" __global__ void __launch_bounds__(256, 1)
gin_layer(const float* __restrict__ in, float* __restrict__ out,
          const float* __restrict__ W1, const float* __restrict__ b1,
          const float* __restrict__ W2, const float* __restrict__ b2,
          const float* __restrict__ gamma, const float* __restrict__ beta,
          const float* __restrict__ mean, const float* __restrict__ var,
          const int* __restrict__ batch, int fusePool) {
    extern __shared__ float sm[];
    float* Ws1 = sm;
    float* Ws2 = sm + 16384;
    float* Ts  = sm + 32768;

    const int tid  = threadIdx.x;
    const int lane = tid & 31;
    const int wid  = tid >> 5;
    const int tcol = tid & 15;
    const int trow = tid >> 4;
    const int c0   = tcol * 8;
    const int r0   = trow * 8;

    // stage both weight matrices once per CTA
    for (int i = tid; i < 4096; i += 256) {
        ((float4*)Ws1)[i] = ((const float4*)W1)[i];
        ((float4*)Ws2)[i] = ((const float4*)W2)[i];
    }

    // per-column epilogue constants (registers, computed once)
    float bias1[8], bias2[8], scl[8], mu[8], bet[8];
    #pragma unroll
    for (int j = 0; j < 8; j++) {
        bias1[j] = b1[c0 + j];
        bias2[j] = b2[c0 + j];
        float vr = var[c0 + j];
        scl[j]   = gamma[c0 + j] * rsqrtf(vr + BN_EPS);
        mu[j]    = mean[c0 + j];
        bet[j]   = beta[c0 + j];
    }
    __syncthreads();

    const float4* in4 = (const float4*)in;

    for (int tile = blockIdx.x; tile < NT2; tile += gridDim.x) {
        const int row0 = tile * TR;

        // ---- fused aggregation: A[r] = in[row] + sum_{j in nbr(row)} in[j]
        // 8 warps x 16 rows; lane covers float4 chunk `lane` of the 128-dim row
        {
            int rbeg = wid * 16;
            for (int rl = rbeg; rl < rbeg + 16; rl++) {
                int row = row0 + rl;
                float4 acc = make_float4(0.f, 0.f, 0.f, 0.f);
                if (row < Nn) {
                    acc = in4[row * 32 + lane];
                    int s = g_rowoff[row], e = g_rowoff[row + 1];
                    for (int k = s; k < e; k++) {
                        float4 v = __ldg(&in4[g_col[k] * 32 + lane]);
                        acc.x += v.x; acc.y += v.y; acc.z += v.z; acc.w += v.w;
                    }
                }
                *(float4*)&Ts[rl * TSTR + lane * 4] = acc;
            }
        }
        __syncthreads();

        unsigned long long acc[8][4];

        // ---- GEMM1: B = relu(A @ W1 + b1) ----
        #pragma unroll
        for (int i = 0; i < 8; i++) {
            acc[i][0] = pack2(bias1[0], bias1[1]);
            acc[i][1] = pack2(bias1[2], bias1[3]);
            acc[i][2] = pack2(bias1[4], bias1[5]);
            acc[i][3] = pack2(bias1[6], bias1[7]);
        }
        #pragma unroll 4
        for (int k = 0; k < 128; k++) {
            ulonglong2 wA = *(const ulonglong2*)&Ws1[k * 128 + c0];
            ulonglong2 wB = *(const ulonglong2*)&Ws1[k * 128 + c0 + 4];
            #pragma unroll
            for (int i = 0; i < 8; i++) {
                unsigned long long a2 = pack_dup(Ts[(r0 + i) * TSTR + k]);
                FMA2(acc[i][0], a2, wA.x);
                FMA2(acc[i][1], a2, wA.y);
                FMA2(acc[i][2], a2, wB.x);
                FMA2(acc[i][3], a2, wB.y);
            }
        }
        __syncthreads();   // all GEMM1 reads of Ts complete
        #pragma unroll
        for (int i = 0; i < 8; i++) {
            #pragma unroll
            for (int p = 0; p < 4; p++) {
                float2 v = unpack2(acc[i][p]);
                v.x = fmaxf(v.x, 0.f);
                v.y = fmaxf(v.y, 0.f);
                *(float2*)&Ts[(r0 + i) * TSTR + c0 + 2 * p] = v;
            }
        }
        __syncthreads();

        // ---- GEMM2: C = BN(relu(B @ W2 + b2)) ----
        #pragma unroll
        for (int i = 0; i < 8; i++) {
            acc[i][0] = pack2(bias2[0], bias2[1]);
            acc[i][1] = pack2(bias2[2], bias2[3]);
            acc[i][2] = pack2(bias2[4], bias2[5]);
            acc[i][3] = pack2(bias2[6], bias2[7]);
        }
        #pragma unroll 4
        for (int k = 0; k < 128; k++) {
            ulonglong2 wA = *(const ulonglong2*)&Ws2[k * 128 + c0];
            ulonglong2 wB = *(const ulonglong2*)&Ws2[k * 128 + c0 + 4];
            #pragma unroll
            for (int i = 0; i < 8; i++) {
                unsigned long long a2 = pack_dup(Ts[(r0 + i) * TSTR + k]);
                FMA2(acc[i][0], a2, wA.x);
                FMA2(acc[i][1], a2, wA.y);
                FMA2(acc[i][2], a2, wB.x);
                FMA2(acc[i][3], a2, wB.y);
            }
        }

        // ---- epilogue: relu + BN, then store or grouped pool-atomics ----
        if (!fusePool) {
            #pragma unroll
            for (int i = 0; i < 8; i++) {
                int row = row0 + r0 + i;
                if (row < Nn) {
                    float o[8];
                    #pragma unroll
                    for (int p = 0; p < 4; p++) {
                        float2 v = unpack2(acc[i][p]);
                        o[2*p]   = (fmaxf(v.x, 0.f) - mu[2*p])   * scl[2*p]   + bet[2*p];
                        o[2*p+1] = (fmaxf(v.y, 0.f) - mu[2*p+1]) * scl[2*p+1] + bet[2*p+1];
                    }
                    *(float4*)&out[row * 128 + c0]     = make_float4(o[0], o[1], o[2], o[3]);
                    *(float4*)&out[row * 128 + c0 + 4] = make_float4(o[4], o[5], o[6], o[7]);
                }
            }
        } else {
            float ps[8] = {0.f,0.f,0.f,0.f,0.f,0.f,0.f,0.f};
            int curg = -1;
            #pragma unroll
            for (int i = 0; i < 8; i++) {
                int row = row0 + r0 + i;
                if (row >= Nn) continue;
                int g = batch[row];
                if (g != curg) {
                    if (curg >= 0) {
                        float* dst = &g_pooled[curg * 128 + c0];
                        #pragma unroll
                        for (int j = 0; j < 8; j++) { atomicAdd(dst + j, ps[j]); ps[j] = 0.f; }
                    }
                    curg = g;
                }
                #pragma unroll
                for (int p = 0; p < 4; p++) {
                    float2 v = unpack2(acc[i][p]);
                    ps[2*p]   += (fmaxf(v.x, 0.f) - mu[2*p])   * scl[2*p]   + bet[2*p];
                    ps[2*p+1] += (fmaxf(v.y, 0.f) - mu[2*p+1]) * scl[2*p+1] + bet[2*p+1];
                }
            }
            if (curg >= 0) {
                float* dst = &g_pooled[curg * 128 + c0];
                #pragma unroll
                for (int j = 0; j < 8; j++) atomicAdd(dst + j, ps[j]);
            }
        }
        __syncthreads();   // protect Ts before next tile's aggregation writes
    }
}

// ---------------- layer 1 MLP (input dim 2, unchanged working path) ----------
extern "C" __global__ void __launch_bounds__(256, 1)
layer1_mlp(float* __restrict__ out,
           const float* __restrict__ W1, const float* __restrict__ b1,
           const float* __restrict__ W2, const float* __restrict__ b2,
           const float* __restrict__ gamma, const float* __restrict__ beta,
           const float* __restrict__ mean, const float* __restrict__ var) {
    extern __shared__ float sm[];
    float* Ws2 = sm;
    float* Bsm = sm + 16384;
    float* tt  = Bsm + MS * AS;

    int tid = threadIdx.x;
    for (int i = tid; i < 4096; i += 256)
        ((float4*)Ws2)[i] = ((const float4*)W2)[i];

    int row0 = blockIdx.x * MS;
    if (tid < 128) {
        int r = tid >> 1;
        tt[tid] = (row0 + r < Nn) ? g_T2[row0 * 2 + tid] : 0.f;
    }
    __syncthreads();

    int tcol = tid & 15;
    int trow = tid >> 4;
    int c0 = tcol * 8;
    int r0 = trow * 4;

    {
        float4 wa0 = *(const float4*)&W1[c0];
        float4 wa1 = *(const float4*)&W1[c0 + 4];
        float4 wb0 = *(const float4*)&W1[128 + c0];
        float4 wb1 = *(const float4*)&W1[128 + c0 + 4];
        float4 bb0 = *(const float4*)&b1[c0];
        float4 bb1 = *(const float4*)&b1[c0 + 4];
        #pragma unroll
        for (int i = 0; i < 4; i++) {
            float t0 = tt[(r0 + i) * 2];
            float t1 = tt[(r0 + i) * 2 + 1];
            float o[8];
            o[0] = fmaf(t0, wa0.x, fmaf(t1, wb0.x, bb0.x));
            o[1] = fmaf(t0, wa0.y, fmaf(t1, wb0.y, bb0.y));
            o[2] = fmaf(t0, wa0.z, fmaf(t1, wb0.z, bb0.z));
            o[3] = fmaf(t0, wa0.w, fmaf(t1, wb0.w, bb0.w));
            o[4] = fmaf(t0, wa1.x, fmaf(t1, wb1.x, bb1.x));
            o[5] = fmaf(t0, wa1.y, fmaf(t1, wb1.y, bb1.y));
            o[6] = fmaf(t0, wa1.z, fmaf(t1, wb1.z, bb1.z));
            o[7] = fmaf(t0, wa1.w, fmaf(t1, wb1.w, bb1.w));
            #pragma unroll
            for (int j = 0; j < 8; j++) o[j] = fmaxf(o[j], 0.f);
            *(float4*)&Bsm[(r0 + i) * AS + c0]     = make_float4(o[0], o[1], o[2], o[3]);
            *(float4*)&Bsm[(r0 + i) * AS + c0 + 4] = make_float4(o[4], o[5], o[6], o[7]);
        }
    }
    __syncthreads();

    float acc[4][8];
    {
        float4 bb0 = *(const float4*)&b2[c0];
        float4 bb1 = *(const float4*)&b2[c0 + 4];
        #pragma unroll
        for (int i = 0; i < 4; i++) {
            acc[i][0] = bb0.x; acc[i][1] = bb0.y; acc[i][2] = bb0.z; acc[i][3] = bb0.w;
            acc[i][4] = bb1.x; acc[i][5] = bb1.y; acc[i][6] = bb1.z; acc[i][7] = bb1.w;
        }
        #pragma unroll 4
        for (int k = 0; k < 128; k++) {
            float a[4];
            #pragma unroll
            for (int i = 0; i < 4; i++) a[i] = Bsm[(r0 + i) * AS + k];
            float4 w0 = *(float4*)&Ws2[k * 128 + c0];
            float4 w1 = *(float4*)&Ws2[k * 128 + c0 + 4];
            #pragma unroll
            for (int i = 0; i < 4; i++) {
                acc[i][0] = fmaf(a[i], w0.x, acc[i][0]);
                acc[i][1] = fmaf(a[i], w0.y, acc[i][1]);
                acc[i][2] = fmaf(a[i], w0.z, acc[i][2]);
                acc[i][3] = fmaf(a[i], w0.w, acc[i][3]);
                acc[i][4] = fmaf(a[i], w1.x, acc[i][4]);
                acc[i][5] = fmaf(a[i], w1.y, acc[i][5]);
                acc[i][6] = fmaf(a[i], w1.z, acc[i][6]);
                acc[i][7] = fmaf(a[i], w1.w, acc[i][7]);
            }
        }
        float scl[8], mu[8], bt[8];
        {
            float4 gm0 = *(const float4*)&gamma[c0], gm1 = *(const float4*)&gamma[c0 + 4];
            float4 bt0 = *(const float4*)&beta[c0],  bt1 = *(const float4*)&beta[c0 + 4];
            float4 mn0 = *(const float4*)&mean[c0],  mn1 = *(const float4*)&mean[c0 + 4];
            float4 vr0 = *(const float4*)&var[c0],   vr1 = *(const float4*)&var[c0 + 4];
            scl[0]=gm0.x*rsqrtf(vr0.x+BN_EPS); scl[1]=gm0.y*rsqrtf(vr0.y+BN_EPS);
            scl[2]=gm0.z*rsqrtf(vr0.z+BN_EPS); scl[3]=gm0.w*rsqrtf(vr0.w+BN_EPS);
            scl[4]=gm1.x*rsqrtf(vr1.x+BN_EPS); scl[5]=gm1.y*rsqrtf(vr1.y+BN_EPS);
            scl[6]=gm1.z*rsqrtf(vr1.z+BN_EPS); scl[7]=gm1.w*rsqrtf(vr1.w+BN_EPS);
            mu[0]=mn0.x; mu[1]=mn0.y; mu[2]=mn0.z; mu[3]=mn0.w;
            mu[4]=mn1.x; mu[5]=mn1.y; mu[6]=mn1.z; mu[7]=mn1.w;
            bt[0]=bt0.x; bt[1]=bt0.y; bt[2]=bt0.z; bt[3]=bt0.w;
            bt[4]=bt1.x; bt[5]=bt1.y; bt[6]=bt1.z; bt[7]=bt1.w;
        }
        #pragma unroll
        for (int i = 0; i < 4; i++) {
            int row = row0 + r0 + i;
            if (row < Nn) {
                float o[8];
                #pragma unroll
                for (int j = 0; j < 8; j++) {
                    float v = fmaxf(acc[i][j], 0.f);
                    o[j] = (v - mu[j]) * scl[j] + bt[j];
                }
                *(float4*)&out[row * 128 + c0]     = make_float4(o[0], o[1], o[2], o[3]);
                *(float4*)&out[row * 128 + c0 + 4] = make_float4(o[4], o[5], o[6], o[7]);
            }
        }
    }
}

// ---------------- head --------------------------------------------------------
__global__ void head_kernel(const float* __restrict__ lin1W, const float* __restrict__ lin1b,
                            const float* __restrict__ lin2W, const float* __restrict__ lin2b,
                            float* __restrict__ out) {
    int g = blockIdx.x;
    int c = threadIdx.x;
    __shared__ float p[128];
    p[c] = g_pooled[g * 128 + c];
    __syncthreads();
    float v = lin1b[c];
    #pragma unroll 8
    for (int k = 0; k < 128; k++)
        v = fmaf(p[k], lin1W[k * 128 + c], v);
    float partial = fmaxf(v, 0.f) * lin2W[c];
    #pragma unroll
    for (int off = 16; off > 0; off >>= 1)
        partial += __shfl_down_sync(0xffffffffu, partial, off);
    __shared__ float red[4];
    int warp = c >> 5;
    if ((c & 31) == 0) red[warp] = partial;
    __syncthreads();
    if (c == 0)
        out[g] = red[0] + red[1] + red[2] + red[3] + lin2b[0];
}

// ---------------- launcher ----------------------------------------------------
extern "C" void kernel_launch(void* const* d_in, const int* in_sizes, int n_in,
                              void* d_out, int out_size) {
    const float* x      = (const float*)d_in[0];
    const int*   ei     = (const int*)d_in[1];
    const int*   batch  = (const int*)d_in[2];
    const float* c1_W1   = (const float*)d_in[3];
    const float* c1_b1   = (const float*)d_in[4];
    const float* c1_W2   = (const float*)d_in[5];
    const float* c1_b2   = (const float*)d_in[6];
    const float* c1_g    = (const float*)d_in[7];
    const float* c1_be   = (const float*)d_in[8];
    const float* c1_m    = (const float*)d_in[9];
    const float* c1_v    = (const float*)d_in[10];
    const float* cs_W1   = (const float*)d_in[11];
    const float* cs_b1   = (const float*)d_in[12];
    const float* cs_W2   = (const float*)d_in[13];
    const float* cs_b2   = (const float*)d_in[14];
    const float* cs_g    = (const float*)d_in[15];
    const float* cs_be   = (const float*)d_in[16];
    const float* cs_m    = (const float*)d_in[17];
    const float* cs_v    = (const float*)d_in[18];
    const float* lin1W   = (const float*)d_in[19];
    const float* lin1b   = (const float*)d_in[20];
    const float* lin2W   = (const float*)d_in[21];
    const float* lin2b   = (const float*)d_in[22];
    float* out = (float*)d_out;

    float *pBufA = nullptr, *pT = nullptr;
    cudaGetSymbolAddress((void**)&pBufA, g_bufA);
    cudaGetSymbolAddress((void**)&pT, g_T);

    const int SMEM_GIN = (16384 * 2 + TR * TSTR) * 4;   // 198656 B
    const int SMEM_L1  = (16384 + MS * AS + 128) * 4;   //  99840 B
    cudaFuncSetAttribute(gin_layer, cudaFuncAttributeMaxDynamicSharedMemorySize, SMEM_GIN);
    cudaFuncSetAttribute(layer1_mlp, cudaFuncAttributeMaxDynamicSharedMemorySize, SMEM_L1);

    // CSR build
    zero_kernel<<<(Gg * Hh + 255) / 256, 256>>>();
    hist_kernel<<<(Ee + 255) / 256, 256>>>(ei);
    scan_kernel<<<1, 1024>>>();
    fill_kernel<<<(Ee + 255) / 256, 256>>>(ei);

    // layer 1 (input dim 2)
    agg2_kernel<<<(Nn + 255) / 256, 256>>>(x);
    layer1_mlp<<<NTILES, 256, SMEM_L1>>>(pBufA, c1_W1, c1_b1, c1_W2, c1_b2,
                                         c1_g, c1_be, c1_m, c1_v);

    // layers 2..5: persistent fused gather + FFMA2 double-GEMM
    const int HH = Hh * Hh;
    const float* bufs[2] = {pBufA, pT};
    for (int l = 0; l < 4; l++) {
        const float* src = bufs[l & 1];
        float*       dst = (float*)bufs[(l + 1) & 1];
        gin_layer<<<NCTA, 256, SMEM_GIN>>>(src, dst,
                                           cs_W1 + l * HH, cs_b1 + l * Hh,
                                           cs_W2 + l * HH, cs_b2 + l * Hh,
                                           cs_g + l * Hh, cs_be + l * Hh,
                                           cs_m + l * Hh, cs_v + l * Hh,
                                           batch, (l == 3) ? 1 : 0);
    }

    head_kernel<<<Gg, 128>>>(lin1W, lin1b, lin2W, lin2b, out);

    (void)in_sizes; (void)n_in; (void)out_size;
}